// round 9
// baseline (speedup 1.0000x reference)
#include <cuda_runtime.h>
#include <cuda_fp16.h>
#include <cstdint>

#define B_    16
#define CIN   512
#define HH    100
#define WW    100
#define HW    10000
#define E_    256
#define TOPK  100
#define PT_M  64
#define PTILES 157          // ceil(10000/64)

#define SRC_SIZE  (B_ * E_ * HW)
#define POS_OFF   SRC_SIZE
#define POS_SIZE  (B_ * TOPK * E_)
#define TEXT_OFF  (POS_OFF + POS_SIZE)

// ---- scratch (device globals) ----
__device__ float   g_scores[B_ * HW];
__device__ int     g_topk[B_ * TOPK];
__device__ float   g_wbar[CIN];
__device__ float   g_cbar;
__device__ __half  g_convw_h[E_ * CIN];   // fp16 conv_w, [e][c]

// ============================================================
// prep: fp16 weights + wbar/cbar
// ============================================================
__global__ void convh_kernel(const float* __restrict__ conv_w) {
    int i = blockIdx.x * 256 + threadIdx.x;
    g_convw_h[i] = __float2half_rn(conv_w[i]);
}

__global__ void wbar_kernel(const float* __restrict__ conv_w,
                            const float* __restrict__ conv_b) {
    int c = blockIdx.x * 128 + threadIdx.x;
    float s = 0.f;
#pragma unroll 8
    for (int e = 0; e < E_; e++) s += conv_w[e * CIN + c];
    g_wbar[c] = s * (1.f / E_);
    if (blockIdx.x == 0) {
        __shared__ float red[128];
        red[threadIdx.x] = conv_b[threadIdx.x] + conv_b[threadIdx.x + 128];
        __syncthreads();
        for (int s2 = 64; s2 > 0; s2 >>= 1) {
            if (threadIdx.x < s2) red[threadIdx.x] += red[threadIdx.x + s2];
            __syncthreads();
        }
        if (threadIdx.x == 0) g_cbar = red[0] * (1.f / E_);
    }
}

// ============================================================
// main GEMM: fp16 mma m16n8k16, f32 accum
// tile: 64pix x 256e x 32k; convert(kt+1) fused with mma(kt)
// smem 100.4KB -> 2 CTAs/SM
// ============================================================
#define TK 32
#define A32_ST 8192                        // fp32 [32k][64pix]
#define BH_ST  20480                       // fp16 [256e][40k] 80B rows
#define AH_ST  5120                        // fp16 [64pix][40k] 80B rows
#define A32_OFF 0                          // 3 slots
#define BH_OFF  (3 * A32_ST)               // 24576, 3 slots
#define AH_OFF  (BH_OFF + 3 * BH_ST)       // 86016, 2 slots
#define WBAR_OFF (AH_OFF + 2 * AH_ST)      // 96256
#define BIAS_OFF (WBAR_OFF + CIN * 4)      // 98304
#define SRED_OFF (BIAS_OFF + 1024)         // 99328
#define SMEM_TOTAL (SRED_OFF + 1024)       // 100352

__device__ __forceinline__ uint32_t pack_h2(float lo, float hi) {
    uint32_t d;
    asm("cvt.rn.f16x2.f32 %0, %1, %2;" : "=r"(d) : "f"(hi), "f"(lo));
    return d;
}

__device__ __forceinline__ void mma_f16(float* c, const uint32_t* a, const uint32_t* b) {
    asm volatile(
        "mma.sync.aligned.m16n8k16.row.col.f32.f16.f16.f32 "
        "{%0,%1,%2,%3}, {%4,%5,%6,%7}, {%8,%9}, {%0,%1,%2,%3};\n"
        : "+f"(c[0]), "+f"(c[1]), "+f"(c[2]), "+f"(c[3])
        : "r"(a[0]), "r"(a[1]), "r"(a[2]), "r"(a[3]), "r"(b[0]), "r"(b[1]));
}

__global__ void __launch_bounds__(256, 2)
gemm_kernel(const float* __restrict__ feat,
            const float* __restrict__ conv_b,
            float* __restrict__ out) {
    extern __shared__ char smem[];
    const int pt    = blockIdx.x;                 // 0..156
    const int b     = blockIdx.y;                 // 0..15
    const int p0    = pt * PT_M;
    const int valid = min(PT_M, HW - p0);
    const int tid   = threadIdx.x;
    const int warp  = tid >> 5, lane = tid & 31;
    const int wn    = warp * 32;                  // e offset of warp tile

    float* s_wbar = (float*)(smem + WBAR_OFF);
    float* s_bias = (float*)(smem + BIAS_OFF);
    float* s_red  = (float*)(smem + SRED_OFF);
    s_bias[tid] = conv_b[tid];
    s_wbar[tid]       = g_wbar[tid];
    s_wbar[tid + 256] = g_wbar[tid + 256];

    const float*  gA = feat + (size_t)b * CIN * HW + p0;
    const __half* gB = g_convw_h;

    auto issue_stage = [&](int kt, int slot) {
        char* baseA = smem + A32_OFF + slot * A32_ST;
        char* baseB = smem + BH_OFF + slot * BH_ST;
        int c0 = kt * TK;
#pragma unroll
        for (int i = 0; i < 2; i++) {                 // A fp32: 32k x 64pix
            int cid = tid + i * 256;
            int k  = cid >> 4;
            int pc = (cid & 15) << 2;
            const float* src = gA + (size_t)(c0 + k) * HW + pc;
            uint32_t dst = (uint32_t)__cvta_generic_to_shared(baseA + (k * 64 + pc) * 4);
            int sz = (pc < valid) ? 16 : 0;
            asm volatile("cp.async.cg.shared.global [%0], [%1], 16, %2;\n"
                         :: "r"(dst), "l"(src), "r"(sz) : "memory");
        }
#pragma unroll
        for (int i = 0; i < 4; i++) {                 // B fp16: 256e x 32k
            int cid = tid + i * 256;
            int e   = cid >> 2;
            int c16 = cid & 3;
            const __half* src = gB + (size_t)e * CIN + c0 + c16 * 8;
            uint32_t dst = (uint32_t)__cvta_generic_to_shared(baseB + e * 80 + c16 * 16);
            asm volatile("cp.async.cg.shared.global [%0], [%1], 16;\n"
                         :: "r"(dst), "l"(src) : "memory");
        }
    };

    float acc[4][4][4];
#pragma unroll
    for (int mf = 0; mf < 4; mf++)
#pragma unroll
        for (int nf = 0; nf < 4; nf++)
#pragma unroll
            for (int r = 0; r < 4; r++) acc[mf][nf][r] = 0.f;

    float scoreAcc = 0.f;
    const int m_cv = tid & 63;                    // pixel this thread converts
    const int kq   = tid >> 6;                    // k-quarter (0..3), 8 k each

    auto do_convert = [&](int kt) {
        const char* baseA  = smem + A32_OFF + (kt % 3) * A32_ST;
        char*       baseAH = smem + AH_OFF + (kt & 1) * AH_ST;
        const float* a32 = (const float*)baseA + kq * 8 * 64 + m_cv;
        const float* wb  = s_wbar + kt * TK + kq * 8;
        float v[8];
#pragma unroll
        for (int k = 0; k < 8; k++) v[k] = a32[k * 64];
#pragma unroll
        for (int k = 0; k < 8; k++) scoreAcc += v[k] * wb[k];
        uint32_t h2[4];
#pragma unroll
        for (int j = 0; j < 4; j++) h2[j] = pack_h2(v[2 * j], v[2 * j + 1]);
        *(uint4*)(baseAH + m_cv * 80 + kq * 16) = make_uint4(h2[0], h2[1], h2[2], h2[3]);
    };

    issue_stage(0, 0); asm volatile("cp.async.commit_group;\n" ::: "memory");
    issue_stage(1, 1); asm volatile("cp.async.commit_group;\n" ::: "memory");
    asm volatile("cp.async.wait_group 1;\n" ::: "memory");
    __syncthreads();
    do_convert(0);

    for (int kt = 0; kt < 16; kt++) {
        __syncthreads();                          // slot (kt+2)%3 free; AH[(kt+1)&1] free
        if (kt + 2 < 16) issue_stage(kt + 2, (kt + 2) % 3);
        asm volatile("cp.async.commit_group;\n" ::: "memory");
        asm volatile("cp.async.wait_group 1;\n" ::: "memory");
        __syncthreads();                          // stage kt+1 visible

        if (kt + 1 < 16) do_convert(kt + 1);      // fills AH[(kt+1)&1]

        // ---- mma(kt): reads AH[kt&1] + BH[kt%3] ----
        const char* ah = smem + AH_OFF + (kt & 1) * AH_ST;
        const char* bh = smem + BH_OFF + (kt % 3) * BH_ST;
#pragma unroll
        for (int ks = 0; ks < 2; ks++) {
            const int kb = ks * 32 + (lane & 3) * 4;   // byte offset of k pair
            uint32_t afr[4][4];
#pragma unroll
            for (int mf = 0; mf < 4; mf++) {
                int r = mf * 16 + (lane >> 2);
                afr[mf][0] = *(const uint32_t*)(ah + r * 80 + kb);
                afr[mf][1] = *(const uint32_t*)(ah + (r + 8) * 80 + kb);
                afr[mf][2] = *(const uint32_t*)(ah + r * 80 + kb + 16);
                afr[mf][3] = *(const uint32_t*)(ah + (r + 8) * 80 + kb + 16);
            }
            uint32_t bfr[4][2];
#pragma unroll
            for (int nf = 0; nf < 4; nf++) {
                int n = wn + nf * 8 + (lane >> 2);
                bfr[nf][0] = *(const uint32_t*)(bh + n * 80 + kb);
                bfr[nf][1] = *(const uint32_t*)(bh + n * 80 + kb + 16);
            }
#pragma unroll
            for (int mf = 0; mf < 4; mf++)
#pragma unroll
                for (int nf = 0; nf < 4; nf++)
                    mma_f16(acc[mf][nf], afr[mf], bfr[nf]);
        }
    }

    // ---- combine the four k-quarter score accumulators ----
    s_red[tid] = scoreAcc;
    __syncthreads();
    if (tid < valid)
        g_scores[b * HW + p0 + tid] = s_red[tid] + s_red[tid + 64] +
                                      s_red[tid + 128] + s_red[tid + 192] + g_cbar;

    // ---- epilogue ----
    float* outp = out + (size_t)b * E_ * HW + p0;
#pragma unroll
    for (int mf = 0; mf < 4; mf++) {
        int r0 = mf * 16 + (lane >> 2);
#pragma unroll
        for (int nf = 0; nf < 4; nf++) {
            int c0 = wn + nf * 8 + (lane & 3) * 2;
            float b0v = s_bias[c0], b1v = s_bias[c0 + 1];
            if (r0 < valid) {
                outp[(size_t)c0       * HW + r0] = acc[mf][nf][0] + b0v;
                outp[(size_t)(c0 + 1) * HW + r0] = acc[mf][nf][1] + b1v;
            }
            if (r0 + 8 < valid) {
                outp[(size_t)c0       * HW + r0 + 8] = acc[mf][nf][2] + b0v;
                outp[(size_t)(c0 + 1) * HW + r0 + 8] = acc[mf][nf][3] + b1v;
            }
        }
    }
}

// ============================================================
// per-batch top-100 via radix select, parallel bin scans
// ============================================================
#define TPB 1024
__global__ void __launch_bounds__(TPB) topk_kernel() {
    __shared__ uint32_t skey[HW];
    __shared__ int hist[256];
    __shared__ int sscan[256];
    __shared__ int s_pref, s_need, s_cnt, s_idxT;
    __shared__ uint32_t wkey[128];
    __shared__ uint32_t widx[128];

    const int b = blockIdx.x, tid = threadIdx.x;
    const float* sc = g_scores + b * HW;
    for (int i = tid; i < HW; i += TPB) {
        uint32_t bits = __float_as_uint(sc[i]);
        skey[i] = (bits & 0x80000000u) ? ~bits : (bits | 0x80000000u);
    }
    __syncthreads();

    uint32_t prefVal = 0, prefMask = 0;
    int need = TOPK;
    for (int pass = 0; pass < 4; pass++) {
        int shift = 24 - 8 * pass;
        if (tid < 256) hist[tid] = 0;
        __syncthreads();
        for (int i = tid; i < HW; i += TPB) {
            uint32_t k = skey[i];
            if ((k & prefMask) == prefVal)
                atomicAdd(&hist[(k >> shift) & 255], 1);
        }
        __syncthreads();
        if (tid < 256) sscan[tid] = hist[tid];
        __syncthreads();
#pragma unroll
        for (int st = 1; st < 256; st <<= 1) {        // inclusive suffix scan
            int add = (tid < 256 && tid + st < 256) ? sscan[tid + st] : 0;
            __syncthreads();
            if (tid < 256) sscan[tid] += add;
            __syncthreads();
        }
        if (tid < 256) {
            int sfx = sscan[tid], cnt = hist[tid];
            if (sfx >= need && sfx - cnt < need) {
                s_pref = tid;
                s_need = need - (sfx - cnt);
            }
        }
        __syncthreads();
        prefVal |= ((uint32_t)s_pref) << shift;
        prefMask |= 0xFFu << shift;
        need = s_need;
        __syncthreads();
    }
    const uint32_t uT = prefVal;
    const int T = need;

    if (tid < 256) hist[tid] = 0;
    __syncthreads();
    for (int i = tid; i < HW; i += TPB)
        if (skey[i] == uT) atomicAdd(&hist[i >> 7], 1);
    __syncthreads();
    if (tid < 256) sscan[tid] = (tid < 128) ? hist[tid] : 0;
    __syncthreads();
#pragma unroll
    for (int st = 1; st < 128; st <<= 1) {
        int add = (tid < 128 && tid >= st) ? sscan[tid - st] : 0;
        __syncthreads();
        if (tid < 128) sscan[tid] += add;
        __syncthreads();
    }
    if (tid < 128) {
        int pfx = sscan[tid], cnt = hist[tid];
        if (pfx >= T && pfx - cnt < T) {
            s_pref = tid;
            s_need = T - (pfx - cnt);
        }
    }
    __syncthreads();
    const int binA = s_pref, Trem = s_need;

    if (tid < 256) hist[tid] = 0;
    __syncthreads();
    for (int i = tid; i < HW; i += TPB)
        if (skey[i] == uT && (i >> 7) == binA) atomicAdd(&hist[i & 127], 1);
    __syncthreads();
    if (tid < 256) sscan[tid] = (tid < 128) ? hist[tid] : 0;
    __syncthreads();
#pragma unroll
    for (int st = 1; st < 128; st <<= 1) {
        int add = (tid < 128 && tid >= st) ? sscan[tid - st] : 0;
        __syncthreads();
        if (tid < 128) sscan[tid] += add;
        __syncthreads();
    }
    if (tid < 128) {
        int pfx = sscan[tid], cnt = hist[tid];
        if (pfx >= Trem && pfx - cnt < Trem) {
            s_idxT = binA * 128 + tid;
            s_cnt = 0;
        }
    }
    __syncthreads();
    const int idxT = s_idxT;

    for (int i = tid; i < HW; i += TPB) {
        uint32_t k = skey[i];
        if (k > uT || (k == uT && i <= idxT)) {
            int p = atomicAdd(&s_cnt, 1);
            wkey[p] = k;
            widx[p] = (uint32_t)i;
        }
    }
    __syncthreads();
    if (tid >= TOPK && tid < 128) { wkey[tid] = 0; widx[tid] = 0xFFFFFFFFu; }
    __syncthreads();

    for (int size = 2; size <= 128; size <<= 1) {
        for (int stride = size >> 1; stride > 0; stride >>= 1) {
            __syncthreads();
            if (tid < 128) {
                int j = tid ^ stride;
                if (j > tid) {
                    uint64_t ki = ((uint64_t)wkey[tid] << 32) | (uint32_t)(~widx[tid]);
                    uint64_t kj = ((uint64_t)wkey[j]   << 32) | (uint32_t)(~widx[j]);
                    bool up = ((tid & size) == 0);
                    if ((ki > kj) == up) {
                        uint32_t t;
                        t = wkey[tid]; wkey[tid] = wkey[j]; wkey[j] = t;
                        t = widx[tid]; widx[tid] = widx[j]; widx[j] = t;
                    }
                }
            }
        }
    }
    __syncthreads();
    if (tid < TOPK) g_topk[b * TOPK + tid] = (int)widx[127 - tid];
}

// ============================================================
// tail: pos_embed + text_proj
// ============================================================
__global__ void tail_kernel(const float* __restrict__ coord_w,
                            const float* __restrict__ coord_b,
                            const float* __restrict__ text_emb,
                            const float* __restrict__ text_w,
                            const float* __restrict__ text_b,
                            float* __restrict__ out) {
    __shared__ float red[256];
    int blk = blockIdx.x, tid = threadIdx.x;
    if (blk < B_ * TOPK) {
        int b = blk / TOPK, k = blk % TOPK;
        int idx = g_topk[b * TOPK + k];
        float ys = (float)(idx / WW) / (float)HH;
        float xs = (float)(idx % WW) / (float)WW;
        float v = xs * coord_w[tid * 2 + 0] + ys * coord_w[tid * 2 + 1] + coord_b[tid];
        out[POS_OFF + (size_t)(b * TOPK + k) * E_ + tid] = v;
    } else {
        int e = blk - B_ * TOPK;
        float s = 0.f;
        for (int i = tid; i < 786; i += 256) s += text_emb[i] * text_w[e * 786 + i];
        red[tid] = s; __syncthreads();
        for (int k2 = 128; k2 > 0; k2 >>= 1) {
            if (tid < k2) red[tid] += red[tid + k2];
            __syncthreads();
        }
        if (tid == 0) {
            float v = red[0] + text_b[e];
            for (int bb = 0; bb < B_; bb++) out[TEXT_OFF + bb * E_ + e] = v;
        }
    }
}

// ============================================================
extern "C" void kernel_launch(void* const* d_in, const int* in_sizes, int n_in,
                              void* d_out, int out_size) {
    const float* feat     = (const float*)d_in[0];
    const float* text_emb = (const float*)d_in[2];
    const float* conv_w   = (const float*)d_in[3];
    const float* conv_b   = (const float*)d_in[4];
    const float* text_w   = (const float*)d_in[5];
    const float* text_b   = (const float*)d_in[6];
    const float* coord_w  = (const float*)d_in[7];
    const float* coord_b  = (const float*)d_in[8];
    float* out = (float*)d_out;

    cudaFuncSetAttribute(gemm_kernel,
                         cudaFuncAttributeMaxDynamicSharedMemorySize, SMEM_TOTAL);

    convh_kernel<<<E_ * CIN / 256, 256>>>(conv_w);
    wbar_kernel<<<4, 128>>>(conv_w, conv_b);
    dim3 g(PTILES, B_);
    gemm_kernel<<<g, 256, SMEM_TOTAL>>>(feat, conv_b, out);
    topk_kernel<<<B_, TPB>>>();
    tail_kernel<<<B_ * TOPK + E_, 256>>>(coord_w, coord_b,
                                         text_emb, text_w, text_b, out);
}

// round 10
// speedup vs baseline: 1.5143x; 1.5143x over previous
#include <cuda_runtime.h>
#include <cuda_fp16.h>
#include <cstdint>

#define B_    16
#define CIN   512
#define HH    100
#define WW    100
#define HW    10000
#define E_    256
#define TOPK  100
#define PT_M  64
#define PTILES 157          // ceil(10000/64)

#define SRC_SIZE  (B_ * E_ * HW)
#define POS_OFF   SRC_SIZE
#define POS_SIZE  (B_ * TOPK * E_)
#define TEXT_OFF  (POS_OFF + POS_SIZE)

// ---- scratch (device globals) ----
__device__ float   g_scores[B_ * HW];
__device__ int     g_topk[B_ * TOPK];
__device__ float   g_wbar[CIN];
__device__ float   g_cbar;
__device__ __half  g_convw_h[E_ * CIN];   // fp16 conv_w, [e][c]

// ============================================================
// prep: fp16 weights + wbar/cbar
// ============================================================
__global__ void convh_kernel(const float* __restrict__ conv_w) {
    int i = blockIdx.x * 256 + threadIdx.x;
    g_convw_h[i] = __float2half_rn(conv_w[i]);
}

__global__ void wbar_kernel(const float* __restrict__ conv_w,
                            const float* __restrict__ conv_b) {
    int c = blockIdx.x * 128 + threadIdx.x;
    float s = 0.f;
#pragma unroll 8
    for (int e = 0; e < E_; e++) s += conv_w[e * CIN + c];
    g_wbar[c] = s * (1.f / E_);
    if (blockIdx.x == 0) {
        __shared__ float red[128];
        red[threadIdx.x] = conv_b[threadIdx.x] + conv_b[threadIdx.x + 128];
        __syncthreads();
        for (int s2 = 64; s2 > 0; s2 >>= 1) {
            if (threadIdx.x < s2) red[threadIdx.x] += red[threadIdx.x + s2];
            __syncthreads();
        }
        if (threadIdx.x == 0) g_cbar = red[0] * (1.f / E_);
    }
}

// ============================================================
// main GEMM: fp16 mma m16n8k16, f32 accum
// tile: 64pix x 256e x 32k; convert(kt+1) fused with mma(kt)
// smem 100.4KB -> 2 CTAs/SM
// ============================================================
#define TK 32
#define A32_ST 8192                        // fp32 [32k][64pix]
#define BH_ST  20480                       // fp16 [256e][40k] 80B rows
#define AH_ST  5120                        // fp16 [64pix][40k] 80B rows
#define A32_OFF 0                          // 3 slots
#define BH_OFF  (3 * A32_ST)               // 24576, 3 slots
#define AH_OFF  (BH_OFF + 3 * BH_ST)       // 86016, 2 slots
#define WBAR_OFF (AH_OFF + 2 * AH_ST)      // 96256
#define BIAS_OFF (WBAR_OFF + CIN * 4)      // 98304
#define SRED_OFF (BIAS_OFF + 1024)         // 99328
#define SMEM_TOTAL (SRED_OFF + 1024)       // 100352

__device__ __forceinline__ uint32_t pack_h2(float lo, float hi) {
    uint32_t d;
    asm("cvt.rn.f16x2.f32 %0, %1, %2;" : "=r"(d) : "f"(hi), "f"(lo));
    return d;
}

__device__ __forceinline__ void mma_f16(float* c, const uint32_t* a, const uint32_t* b) {
    asm volatile(
        "mma.sync.aligned.m16n8k16.row.col.f32.f16.f16.f32 "
        "{%0,%1,%2,%3}, {%4,%5,%6,%7}, {%8,%9}, {%0,%1,%2,%3};\n"
        : "+f"(c[0]), "+f"(c[1]), "+f"(c[2]), "+f"(c[3])
        : "r"(a[0]), "r"(a[1]), "r"(a[2]), "r"(a[3]), "r"(b[0]), "r"(b[1]));
}

__global__ void __launch_bounds__(256, 2)
gemm_kernel(const float* __restrict__ feat,
            const float* __restrict__ conv_b,
            float* __restrict__ out) {
    extern __shared__ char smem[];
    const int pt    = blockIdx.x;                 // 0..156
    const int b     = blockIdx.y;                 // 0..15
    const int p0    = pt * PT_M;
    const int valid = min(PT_M, HW - p0);
    const int tid   = threadIdx.x;
    const int warp  = tid >> 5, lane = tid & 31;
    const int wn    = warp * 32;                  // e offset of warp tile

    float* s_wbar = (float*)(smem + WBAR_OFF);
    float* s_bias = (float*)(smem + BIAS_OFF);
    float* s_red  = (float*)(smem + SRED_OFF);
    s_bias[tid] = conv_b[tid];
    s_wbar[tid]       = g_wbar[tid];
    s_wbar[tid + 256] = g_wbar[tid + 256];

    const float*  gA = feat + (size_t)b * CIN * HW + p0;
    const __half* gB = g_convw_h;

    auto issue_stage = [&](int kt, int slot) {
        char* baseA = smem + A32_OFF + slot * A32_ST;
        char* baseB = smem + BH_OFF + slot * BH_ST;
        int c0 = kt * TK;
#pragma unroll
        for (int i = 0; i < 2; i++) {                 // A fp32: 32k x 64pix
            int cid = tid + i * 256;
            int k  = cid >> 4;
            int pc = (cid & 15) << 2;
            const float* src = gA + (size_t)(c0 + k) * HW + pc;
            uint32_t dst = (uint32_t)__cvta_generic_to_shared(baseA + (k * 64 + pc) * 4);
            int sz = (pc < valid) ? 16 : 0;
            asm volatile("cp.async.cg.shared.global [%0], [%1], 16, %2;\n"
                         :: "r"(dst), "l"(src), "r"(sz) : "memory");
        }
#pragma unroll
        for (int i = 0; i < 4; i++) {                 // B fp16: 256e x 32k
            int cid = tid + i * 256;
            int e   = cid >> 2;
            int c16 = cid & 3;
            const __half* src = gB + (size_t)e * CIN + c0 + c16 * 8;
            uint32_t dst = (uint32_t)__cvta_generic_to_shared(baseB + e * 80 + c16 * 16);
            asm volatile("cp.async.cg.shared.global [%0], [%1], 16;\n"
                         :: "r"(dst), "l"(src) : "memory");
        }
    };

    float acc[4][4][4];
#pragma unroll
    for (int mf = 0; mf < 4; mf++)
#pragma unroll
        for (int nf = 0; nf < 4; nf++)
#pragma unroll
            for (int r = 0; r < 4; r++) acc[mf][nf][r] = 0.f;

    float scoreAcc = 0.f;
    const int m_cv = tid & 63;                    // pixel this thread converts
    const int kq   = tid >> 6;                    // k-quarter (0..3), 8 k each

    auto do_convert = [&](int kt) {
        const char* baseA  = smem + A32_OFF + (kt % 3) * A32_ST;
        char*       baseAH = smem + AH_OFF + (kt & 1) * AH_ST;
        const float* a32 = (const float*)baseA + kq * 8 * 64 + m_cv;
        const float* wb  = s_wbar + kt * TK + kq * 8;
        float v[8];
#pragma unroll
        for (int k = 0; k < 8; k++) v[k] = a32[k * 64];
#pragma unroll
        for (int k = 0; k < 8; k++) scoreAcc += v[k] * wb[k];
        uint32_t h2[4];
#pragma unroll
        for (int j = 0; j < 4; j++) h2[j] = pack_h2(v[2 * j], v[2 * j + 1]);
        *(uint4*)(baseAH + m_cv * 80 + kq * 16) = make_uint4(h2[0], h2[1], h2[2], h2[3]);
    };

    issue_stage(0, 0); asm volatile("cp.async.commit_group;\n" ::: "memory");
    issue_stage(1, 1); asm volatile("cp.async.commit_group;\n" ::: "memory");
    asm volatile("cp.async.wait_group 1;\n" ::: "memory");
    __syncthreads();
    do_convert(0);

    for (int kt = 0; kt < 16; kt++) {
        __syncthreads();                          // slot (kt+2)%3 free; AH[(kt+1)&1] free
        if (kt + 2 < 16) issue_stage(kt + 2, (kt + 2) % 3);
        asm volatile("cp.async.commit_group;\n" ::: "memory");
        asm volatile("cp.async.wait_group 1;\n" ::: "memory");
        __syncthreads();                          // stage kt+1 visible

        if (kt + 1 < 16) do_convert(kt + 1);      // fills AH[(kt+1)&1]

        // ---- mma(kt): reads AH[kt&1] + BH[kt%3] ----
        const char* ah = smem + AH_OFF + (kt & 1) * AH_ST;
        const char* bh = smem + BH_OFF + (kt % 3) * BH_ST;
#pragma unroll
        for (int ks = 0; ks < 2; ks++) {
            const int kb = ks * 32 + (lane & 3) * 4;   // byte offset of k pair
            uint32_t afr[4][4];
#pragma unroll
            for (int mf = 0; mf < 4; mf++) {
                int r = mf * 16 + (lane >> 2);
                afr[mf][0] = *(const uint32_t*)(ah + r * 80 + kb);
                afr[mf][1] = *(const uint32_t*)(ah + (r + 8) * 80 + kb);
                afr[mf][2] = *(const uint32_t*)(ah + r * 80 + kb + 16);
                afr[mf][3] = *(const uint32_t*)(ah + (r + 8) * 80 + kb + 16);
            }
            uint32_t bfr[4][2];
#pragma unroll
            for (int nf = 0; nf < 4; nf++) {
                int n = wn + nf * 8 + (lane >> 2);
                bfr[nf][0] = *(const uint32_t*)(bh + n * 80 + kb);
                bfr[nf][1] = *(const uint32_t*)(bh + n * 80 + kb + 16);
            }
#pragma unroll
            for (int mf = 0; mf < 4; mf++)
#pragma unroll
                for (int nf = 0; nf < 4; nf++)
                    mma_f16(acc[mf][nf], afr[mf], bfr[nf]);
        }
    }

    // ---- combine the four k-quarter score accumulators ----
    s_red[tid] = scoreAcc;
    __syncthreads();
    if (tid < valid)
        g_scores[b * HW + p0 + tid] = s_red[tid] + s_red[tid + 64] +
                                      s_red[tid + 128] + s_red[tid + 192] + g_cbar;

    // ---- epilogue ----
    float* outp = out + (size_t)b * E_ * HW + p0;
#pragma unroll
    for (int mf = 0; mf < 4; mf++) {
        int r0 = mf * 16 + (lane >> 2);
#pragma unroll
        for (int nf = 0; nf < 4; nf++) {
            int c0 = wn + nf * 8 + (lane & 3) * 2;
            float b0v = s_bias[c0], b1v = s_bias[c0 + 1];
            if (r0 < valid) {
                outp[(size_t)c0       * HW + r0] = acc[mf][nf][0] + b0v;
                outp[(size_t)(c0 + 1) * HW + r0] = acc[mf][nf][1] + b1v;
            }
            if (r0 + 8 < valid) {
                outp[(size_t)c0       * HW + r0 + 8] = acc[mf][nf][2] + b0v;
                outp[(size_t)(c0 + 1) * HW + r0 + 8] = acc[mf][nf][3] + b1v;
            }
        }
    }
}

// ============================================================
// per-batch top-100 via radix select, parallel bin scans
// ============================================================
#define TPB 1024
__global__ void __launch_bounds__(TPB) topk_kernel() {
    __shared__ uint32_t skey[HW];
    __shared__ int hist[256];
    __shared__ int sscan[256];
    __shared__ int s_pref, s_need, s_cnt, s_idxT;
    __shared__ uint32_t wkey[128];
    __shared__ uint32_t widx[128];

    const int b = blockIdx.x, tid = threadIdx.x;
    const float* sc = g_scores + b * HW;
    for (int i = tid; i < HW; i += TPB) {
        uint32_t bits = __float_as_uint(sc[i]);
        skey[i] = (bits & 0x80000000u) ? ~bits : (bits | 0x80000000u);
    }
    __syncthreads();

    uint32_t prefVal = 0, prefMask = 0;
    int need = TOPK;
    for (int pass = 0; pass < 4; pass++) {
        int shift = 24 - 8 * pass;
        if (tid < 256) hist[tid] = 0;
        __syncthreads();
        for (int i = tid; i < HW; i += TPB) {
            uint32_t k = skey[i];
            if ((k & prefMask) == prefVal)
                atomicAdd(&hist[(k >> shift) & 255], 1);
        }
        __syncthreads();
        if (tid < 256) sscan[tid] = hist[tid];
        __syncthreads();
#pragma unroll
        for (int st = 1; st < 256; st <<= 1) {        // inclusive suffix scan
            int add = (tid < 256 && tid + st < 256) ? sscan[tid + st] : 0;
            __syncthreads();
            if (tid < 256) sscan[tid] += add;
            __syncthreads();
        }
        if (tid < 256) {
            int sfx = sscan[tid], cnt = hist[tid];
            if (sfx >= need && sfx - cnt < need) {
                s_pref = tid;
                s_need = need - (sfx - cnt);
            }
        }
        __syncthreads();
        prefVal |= ((uint32_t)s_pref) << shift;
        prefMask |= 0xFFu << shift;
        need = s_need;
        __syncthreads();
    }
    const uint32_t uT = prefVal;
    const int T = need;

    if (tid < 256) hist[tid] = 0;
    __syncthreads();
    for (int i = tid; i < HW; i += TPB)
        if (skey[i] == uT) atomicAdd(&hist[i >> 7], 1);
    __syncthreads();
    if (tid < 256) sscan[tid] = (tid < 128) ? hist[tid] : 0;
    __syncthreads();
#pragma unroll
    for (int st = 1; st < 128; st <<= 1) {
        int add = (tid < 128 && tid >= st) ? sscan[tid - st] : 0;
        __syncthreads();
        if (tid < 128) sscan[tid] += add;
        __syncthreads();
    }
    if (tid < 128) {
        int pfx = sscan[tid], cnt = hist[tid];
        if (pfx >= T && pfx - cnt < T) {
            s_pref = tid;
            s_need = T - (pfx - cnt);
        }
    }
    __syncthreads();
    const int binA = s_pref, Trem = s_need;

    if (tid < 256) hist[tid] = 0;
    __syncthreads();
    for (int i = tid; i < HW; i += TPB)
        if (skey[i] == uT && (i >> 7) == binA) atomicAdd(&hist[i & 127], 1);
    __syncthreads();
    if (tid < 256) sscan[tid] = (tid < 128) ? hist[tid] : 0;
    __syncthreads();
#pragma unroll
    for (int st = 1; st < 128; st <<= 1) {
        int add = (tid < 128 && tid >= st) ? sscan[tid - st] : 0;
        __syncthreads();
        if (tid < 128) sscan[tid] += add;
        __syncthreads();
    }
    if (tid < 128) {
        int pfx = sscan[tid], cnt = hist[tid];
        if (pfx >= Trem && pfx - cnt < Trem) {
            s_idxT = binA * 128 + tid;
            s_cnt = 0;
        }
    }
    __syncthreads();
    const int idxT = s_idxT;

    for (int i = tid; i < HW; i += TPB) {
        uint32_t k = skey[i];
        if (k > uT || (k == uT && i <= idxT)) {
            int p = atomicAdd(&s_cnt, 1);
            wkey[p] = k;
            widx[p] = (uint32_t)i;
        }
    }
    __syncthreads();
    if (tid >= TOPK && tid < 128) { wkey[tid] = 0; widx[tid] = 0xFFFFFFFFu; }
    __syncthreads();

    for (int size = 2; size <= 128; size <<= 1) {
        for (int stride = size >> 1; stride > 0; stride >>= 1) {
            __syncthreads();
            if (tid < 128) {
                int j = tid ^ stride;
                if (j > tid) {
                    uint64_t ki = ((uint64_t)wkey[tid] << 32) | (uint32_t)(~widx[tid]);
                    uint64_t kj = ((uint64_t)wkey[j]   << 32) | (uint32_t)(~widx[j]);
                    bool up = ((tid & size) == 0);
                    if ((ki > kj) == up) {
                        uint32_t t;
                        t = wkey[tid]; wkey[tid] = wkey[j]; wkey[j] = t;
                        t = widx[tid]; widx[tid] = widx[j]; widx[j] = t;
                    }
                }
            }
        }
    }
    __syncthreads();
    if (tid < TOPK) g_topk[b * TOPK + tid] = (int)widx[127 - tid];
}

// ============================================================
// tail: pos_embed + text_proj
// ============================================================
__global__ void tail_kernel(const float* __restrict__ coord_w,
                            const float* __restrict__ coord_b,
                            const float* __restrict__ text_emb,
                            const float* __restrict__ text_w,
                            const float* __restrict__ text_b,
                            float* __restrict__ out) {
    __shared__ float red[256];
    int blk = blockIdx.x, tid = threadIdx.x;
    if (blk < B_ * TOPK) {
        int b = blk / TOPK, k = blk % TOPK;
        int idx = g_topk[b * TOPK + k];
        float ys = (float)(idx / WW) / (float)HH;
        float xs = (float)(idx % WW) / (float)WW;
        float v = xs * coord_w[tid * 2 + 0] + ys * coord_w[tid * 2 + 1] + coord_b[tid];
        out[POS_OFF + (size_t)(b * TOPK + k) * E_ + tid] = v;
    } else {
        int e = blk - B_ * TOPK;
        float s = 0.f;
        for (int i = tid; i < 786; i += 256) s += text_emb[i] * text_w[e * 786 + i];
        red[tid] = s; __syncthreads();
        for (int k2 = 128; k2 > 0; k2 >>= 1) {
            if (tid < k2) red[tid] += red[tid + k2];
            __syncthreads();
        }
        if (tid == 0) {
            float v = red[0] + text_b[e];
            for (int bb = 0; bb < B_; bb++) out[TEXT_OFF + bb * E_ + e] = v;
        }
    }
}

// ============================================================
extern "C" void kernel_launch(void* const* d_in, const int* in_sizes, int n_in,
                              void* d_out, int out_size) {
    const float* feat     = (const float*)d_in[0];
    const float* text_emb = (const float*)d_in[2];
    const float* conv_w   = (const float*)d_in[3];
    const float* conv_b   = (const float*)d_in[4];
    const float* text_w   = (const float*)d_in[5];
    const float* text_b   = (const float*)d_in[6];
    const float* coord_w  = (const float*)d_in[7];
    const float* coord_b  = (const float*)d_in[8];
    float* out = (float*)d_out;

    cudaFuncSetAttribute(gemm_kernel,
                         cudaFuncAttributeMaxDynamicSharedMemorySize, SMEM_TOTAL);

    convh_kernel<<<E_ * CIN / 256, 256>>>(conv_w);
    wbar_kernel<<<4, 128>>>(conv_w, conv_b);
    dim3 g(PTILES, B_);
    gemm_kernel<<<g, 256, SMEM_TOTAL>>>(feat, conv_b, out);
    topk_kernel<<<B_, TPB>>>();
    tail_kernel<<<B_ * TOPK + E_, 256>>>(coord_w, coord_b,
                                         text_emb, text_w, text_b, out);
}

// round 11
// speedup vs baseline: 1.6673x; 1.1010x over previous
#include <cuda_runtime.h>
#include <cuda_fp16.h>
#include <cstdint>

#define B_    16
#define CIN   512
#define HH    100
#define WW    100
#define HW    10000
#define E_    256
#define TOPK  100
#define PT_M  64
#define PTILES 157          // ceil(10000/64)

#define SRC_SIZE  (B_ * E_ * HW)
#define POS_OFF   SRC_SIZE
#define POS_SIZE  (B_ * TOPK * E_)
#define TEXT_OFF  (POS_OFF + POS_SIZE)

// ---- scratch (device globals) ----
__device__ float   g_scores[B_ * HW];
__device__ int     g_topk[B_ * TOPK];
__device__ float   g_wbar[CIN];
__device__ float   g_cbar;
__device__ __half  g_convw_h[E_ * CIN];   // fp16 conv_w, [e][c]

// ============================================================
// prep: fp16 weights + wbar/cbar
// ============================================================
__global__ void convh_kernel(const float* __restrict__ conv_w) {
    int i = blockIdx.x * 256 + threadIdx.x;
    g_convw_h[i] = __float2half_rn(conv_w[i]);
}

__global__ void wbar_kernel(const float* __restrict__ conv_w,
                            const float* __restrict__ conv_b) {
    int c = blockIdx.x * 128 + threadIdx.x;
    float s = 0.f;
#pragma unroll 8
    for (int e = 0; e < E_; e++) s += conv_w[e * CIN + c];
    g_wbar[c] = s * (1.f / E_);
    if (blockIdx.x == 0) {
        __shared__ float red[128];
        red[threadIdx.x] = conv_b[threadIdx.x] + conv_b[threadIdx.x + 128];
        __syncthreads();
        for (int s2 = 64; s2 > 0; s2 >>= 1) {
            if (threadIdx.x < s2) red[threadIdx.x] += red[threadIdx.x + s2];
            __syncthreads();
        }
        if (threadIdx.x == 0) g_cbar = red[0] * (1.f / E_);
    }
}

// ============================================================
// main GEMM: fp16 mma m16n8k16, f32 accum; ldmatrix fragment loads
// tile: 64pix x 256e x 32k; convert(kt+1) fused with mma(kt)
// smem 100.4KB -> 2 CTAs/SM
// ============================================================
#define TK 32
#define A32_ST 8192                        // fp32 [32k][64pix]
#define BH_ST  20480                       // fp16 [256e][40k] 80B rows
#define AH_ST  5120                        // fp16 [64pix][40k] 80B rows
#define A32_OFF 0                          // 3 slots
#define BH_OFF  (3 * A32_ST)               // 24576, 3 slots
#define AH_OFF  (BH_OFF + 3 * BH_ST)       // 86016, 2 slots
#define WBAR_OFF (AH_OFF + 2 * AH_ST)      // 96256
#define BIAS_OFF (WBAR_OFF + CIN * 4)      // 98304
#define SRED_OFF (BIAS_OFF + 1024)         // 99328
#define SMEM_TOTAL (SRED_OFF + 1024)       // 100352

__device__ __forceinline__ uint32_t pack_h2(float lo, float hi) {
    uint32_t d;
    asm("cvt.rn.f16x2.f32 %0, %1, %2;" : "=r"(d) : "f"(hi), "f"(lo));
    return d;
}

__device__ __forceinline__ void mma_f16(float* c, const uint32_t* a, const uint32_t* b) {
    asm volatile(
        "mma.sync.aligned.m16n8k16.row.col.f32.f16.f16.f32 "
        "{%0,%1,%2,%3}, {%4,%5,%6,%7}, {%8,%9}, {%0,%1,%2,%3};\n"
        : "+f"(c[0]), "+f"(c[1]), "+f"(c[2]), "+f"(c[3])
        : "r"(a[0]), "r"(a[1]), "r"(a[2]), "r"(a[3]), "r"(b[0]), "r"(b[1]));
}

__device__ __forceinline__ void ldsm_x4(uint32_t& r0, uint32_t& r1,
                                        uint32_t& r2, uint32_t& r3,
                                        const void* p) {
    uint32_t a = (uint32_t)__cvta_generic_to_shared(p);
    asm volatile("ldmatrix.sync.aligned.m8n8.x4.shared.b16 {%0,%1,%2,%3}, [%4];"
                 : "=r"(r0), "=r"(r1), "=r"(r2), "=r"(r3) : "r"(a));
}

__global__ void __launch_bounds__(256, 2)
gemm_kernel(const float* __restrict__ feat,
            const float* __restrict__ conv_b,
            float* __restrict__ out) {
    extern __shared__ char smem[];
    const int pt    = blockIdx.x;                 // 0..156
    const int b     = blockIdx.y;                 // 0..15
    const int p0    = pt * PT_M;
    const int valid = min(PT_M, HW - p0);
    const int tid   = threadIdx.x;
    const int warp  = tid >> 5, lane = tid & 31;
    const int wn    = warp * 32;                  // e offset of warp tile

    float* s_wbar = (float*)(smem + WBAR_OFF);
    float* s_bias = (float*)(smem + BIAS_OFF);
    float* s_red  = (float*)(smem + SRED_OFF);
    s_bias[tid] = conv_b[tid];
    s_wbar[tid]       = g_wbar[tid];
    s_wbar[tid + 256] = g_wbar[tid + 256];

    const float*  gA = feat + (size_t)b * CIN * HW + p0;
    const __half* gB = g_convw_h;

    auto issue_stage = [&](int kt, int slot) {
        char* baseA = smem + A32_OFF + slot * A32_ST;
        char* baseB = smem + BH_OFF + slot * BH_ST;
        int c0 = kt * TK;
#pragma unroll
        for (int i = 0; i < 2; i++) {                 // A fp32: 32k x 64pix
            int cid = tid + i * 256;
            int k  = cid >> 4;
            int pc = (cid & 15) << 2;
            const float* src = gA + (size_t)(c0 + k) * HW + pc;
            uint32_t dst = (uint32_t)__cvta_generic_to_shared(baseA + (k * 64 + pc) * 4);
            int sz = (pc < valid) ? 16 : 0;
            asm volatile("cp.async.cg.shared.global [%0], [%1], 16, %2;\n"
                         :: "r"(dst), "l"(src), "r"(sz) : "memory");
        }
#pragma unroll
        for (int i = 0; i < 4; i++) {                 // B fp16: 256e x 32k
            int cid = tid + i * 256;
            int e   = cid >> 2;
            int c16 = cid & 3;
            const __half* src = gB + (size_t)e * CIN + c0 + c16 * 8;
            uint32_t dst = (uint32_t)__cvta_generic_to_shared(baseB + e * 80 + c16 * 16);
            asm volatile("cp.async.cg.shared.global [%0], [%1], 16;\n"
                         :: "r"(dst), "l"(src) : "memory");
        }
    };

    float acc[4][4][4];
#pragma unroll
    for (int mf = 0; mf < 4; mf++)
#pragma unroll
        for (int nf = 0; nf < 4; nf++)
#pragma unroll
            for (int r = 0; r < 4; r++) acc[mf][nf][r] = 0.f;

    float scoreAcc = 0.f;
    const int m_cv = tid & 63;                    // pixel this thread converts
    const int kq   = tid >> 6;                    // k-quarter (0..3), 8 k each

    auto do_convert = [&](int kt) {
        const char* baseA  = smem + A32_OFF + (kt % 3) * A32_ST;
        char*       baseAH = smem + AH_OFF + (kt & 1) * AH_ST;
        const float* a32 = (const float*)baseA + kq * 8 * 64 + m_cv;
        const float* wb  = s_wbar + kt * TK + kq * 8;
        float v[8];
#pragma unroll
        for (int k = 0; k < 8; k++) v[k] = a32[k * 64];
#pragma unroll
        for (int k = 0; k < 8; k++) scoreAcc += v[k] * wb[k];
        uint32_t h2[4];
#pragma unroll
        for (int j = 0; j < 4; j++) h2[j] = pack_h2(v[2 * j], v[2 * j + 1]);
        *(uint4*)(baseAH + m_cv * 80 + kq * 16) = make_uint4(h2[0], h2[1], h2[2], h2[3]);
    };

    // ldmatrix lane-address components
    const int lm_row = ((lane >> 3) & 1) * 8 + (lane & 7);   // A: row within 16
    const int lm_kb  = (lane >> 4) * 16;                     // A: k-byte within 32
    const int lb_row = (lane >> 4) * 8 + (lane & 7);         // B: n within 16
    const int lb_kb  = ((lane >> 3) & 1) * 16;               // B: k-byte within 32

    issue_stage(0, 0); asm volatile("cp.async.commit_group;\n" ::: "memory");
    issue_stage(1, 1); asm volatile("cp.async.commit_group;\n" ::: "memory");
    asm volatile("cp.async.wait_group 1;\n" ::: "memory");
    __syncthreads();
    do_convert(0);

    for (int kt = 0; kt < 16; kt++) {
        __syncthreads();                          // slot (kt+2)%3 free; AH[(kt+1)&1] free
        if (kt + 2 < 16) issue_stage(kt + 2, (kt + 2) % 3);
        asm volatile("cp.async.commit_group;\n" ::: "memory");
        asm volatile("cp.async.wait_group 1;\n" ::: "memory");
        __syncthreads();                          // stage kt+1 visible

        if (kt + 1 < 16) do_convert(kt + 1);      // fills AH[(kt+1)&1]

        // ---- mma(kt): reads AH[kt&1] + BH[kt%3] via ldmatrix ----
        const char* ah = smem + AH_OFF + (kt & 1) * AH_ST;
        const char* bh = smem + BH_OFF + (kt % 3) * BH_ST;
#pragma unroll
        for (int ks = 0; ks < 2; ks++) {
            uint32_t afr[4][4];
#pragma unroll
            for (int mf = 0; mf < 4; mf++)
                ldsm_x4(afr[mf][0], afr[mf][1], afr[mf][2], afr[mf][3],
                        ah + (mf * 16 + lm_row) * 80 + ks * 32 + lm_kb);
            uint32_t bfr[4][2];
#pragma unroll
            for (int np = 0; np < 2; np++)
                ldsm_x4(bfr[2 * np][0], bfr[2 * np][1],
                        bfr[2 * np + 1][0], bfr[2 * np + 1][1],
                        bh + (wn + np * 16 + lb_row) * 80 + ks * 32 + lb_kb);
#pragma unroll
            for (int mf = 0; mf < 4; mf++)
#pragma unroll
                for (int nf = 0; nf < 4; nf++)
                    mma_f16(acc[mf][nf], afr[mf], bfr[nf]);
        }
    }

    // ---- combine the four k-quarter score accumulators ----
    s_red[tid] = scoreAcc;
    __syncthreads();
    if (tid < valid)
        g_scores[b * HW + p0 + tid] = s_red[tid] + s_red[tid + 64] +
                                      s_red[tid + 128] + s_red[tid + 192] + g_cbar;

    // ---- epilogue ----
    float* outp = out + (size_t)b * E_ * HW + p0;
#pragma unroll
    for (int mf = 0; mf < 4; mf++) {
        int r0 = mf * 16 + (lane >> 2);
#pragma unroll
        for (int nf = 0; nf < 4; nf++) {
            int c0 = wn + nf * 8 + (lane & 3) * 2;
            float b0v = s_bias[c0], b1v = s_bias[c0 + 1];
            if (r0 < valid) {
                outp[(size_t)c0       * HW + r0] = acc[mf][nf][0] + b0v;
                outp[(size_t)(c0 + 1) * HW + r0] = acc[mf][nf][1] + b1v;
            }
            if (r0 + 8 < valid) {
                outp[(size_t)c0       * HW + r0 + 8] = acc[mf][nf][2] + b0v;
                outp[(size_t)(c0 + 1) * HW + r0 + 8] = acc[mf][nf][3] + b1v;
            }
        }
    }
}

// ============================================================
// per-batch top-100 via radix select, single-warp shfl scans
// ============================================================
#define TPB 1024
__global__ void __launch_bounds__(TPB) topk_kernel() {
    __shared__ uint32_t skey[HW];
    __shared__ int hist[256];
    __shared__ int sscan[256];
    __shared__ int s_pref, s_need, s_cnt, s_idxT;
    __shared__ uint32_t wkey[128];
    __shared__ uint32_t widx[128];

    const int b = blockIdx.x, tid = threadIdx.x;
    const float* sc = g_scores + b * HW;
    for (int i = tid; i < HW; i += TPB) {
        uint32_t bits = __float_as_uint(sc[i]);
        skey[i] = (bits & 0x80000000u) ? ~bits : (bits | 0x80000000u);
    }
    __syncthreads();

    // ---- 4x 8-bit radix passes; suffix scan done by warp 0 via shfl ----
    uint32_t prefVal = 0, prefMask = 0;
    int need = TOPK;
    for (int pass = 0; pass < 4; pass++) {
        int shift = 24 - 8 * pass;
        if (tid < 256) hist[tid] = 0;
        __syncthreads();
        for (int i = tid; i < HW; i += TPB) {
            uint32_t k = skey[i];
            if ((k & prefMask) == prefVal)
                atomicAdd(&hist[(k >> shift) & 255], 1);
        }
        __syncthreads();
        if (tid < 32) {                           // warp-0 suffix scan, 8 bins/lane
            int base = tid * 8;
            int v[8]; int tot = 0;
#pragma unroll
            for (int j = 7; j >= 0; j--) { tot += hist[base + j]; v[j] = tot; }
            int sfx = tot;
#pragma unroll
            for (int d = 1; d < 32; d <<= 1) {
                int o = __shfl_down_sync(0xFFFFFFFFu, sfx, d);
                if (tid + d < 32) sfx += o;
            }
            int add = sfx - tot;                  // suffix of lanes > tid
#pragma unroll
            for (int j = 0; j < 8; j++) sscan[base + j] = v[j] + add;
        }
        __syncthreads();
        if (tid < 256) {
            int sfx = sscan[tid], cnt = hist[tid];
            if (sfx >= need && sfx - cnt < need) {    // exactly one bin
                s_pref = tid;
                s_need = need - (sfx - cnt);
            }
        }
        __syncthreads();
        prefVal |= ((uint32_t)s_pref) << shift;
        prefMask |= 0xFFu << shift;
        need = s_need;
        __syncthreads();
    }
    const uint32_t uT = prefVal;
    const int T = need;   // ties (key == uT) to take, smallest index first

    // ---- pass A: coarse index bin (128 bins of 128 idx) ----
    if (tid < 256) hist[tid] = 0;
    __syncthreads();
    for (int i = tid; i < HW; i += TPB)
        if (skey[i] == uT) atomicAdd(&hist[i >> 7], 1);
    __syncthreads();
    if (tid < 32) {                               // warp-0 prefix scan, 4 bins/lane
        int base = tid * 4;
        int v[4]; int tot = 0;
#pragma unroll
        for (int j = 0; j < 4; j++) { tot += hist[base + j]; v[j] = tot; }
        int pfx = tot;
#pragma unroll
        for (int d = 1; d < 32; d <<= 1) {
            int o = __shfl_up_sync(0xFFFFFFFFu, pfx, d);
            if (tid >= d) pfx += o;
        }
        int add = pfx - tot;                      // prefix of lanes < tid
#pragma unroll
        for (int j = 0; j < 4; j++) sscan[base + j] = v[j] + add;
    }
    __syncthreads();
    if (tid < 128) {
        int pfx = sscan[tid], cnt = hist[tid];
        if (pfx >= T && pfx - cnt < T) {
            s_pref = tid;
            s_need = T - (pfx - cnt);
        }
    }
    __syncthreads();
    const int binA = s_pref, Trem = s_need;

    // ---- pass B: fine index within coarse bin ----
    if (tid < 256) hist[tid] = 0;
    __syncthreads();
    for (int i = tid; i < HW; i += TPB)
        if (skey[i] == uT && (i >> 7) == binA) atomicAdd(&hist[i & 127], 1);
    __syncthreads();
    if (tid < 32) {
        int base = tid * 4;
        int v[4]; int tot = 0;
#pragma unroll
        for (int j = 0; j < 4; j++) { tot += hist[base + j]; v[j] = tot; }
        int pfx = tot;
#pragma unroll
        for (int d = 1; d < 32; d <<= 1) {
            int o = __shfl_up_sync(0xFFFFFFFFu, pfx, d);
            if (tid >= d) pfx += o;
        }
        int add = pfx - tot;
#pragma unroll
        for (int j = 0; j < 4; j++) sscan[base + j] = v[j] + add;
    }
    __syncthreads();
    if (tid < 128) {
        int pfx = sscan[tid], cnt = hist[tid];
        if (pfx >= Trem && pfx - cnt < Trem) {
            s_idxT = binA * 128 + tid;
            s_cnt = 0;
        }
    }
    __syncthreads();
    const int idxT = s_idxT;

    // ---- collect the exact 100 winners ----
    for (int i = tid; i < HW; i += TPB) {
        uint32_t k = skey[i];
        if (k > uT || (k == uT && i <= idxT)) {
            int p = atomicAdd(&s_cnt, 1);
            wkey[p] = k;
            widx[p] = (uint32_t)i;
        }
    }
    __syncthreads();
    if (tid >= TOPK && tid < 128) { wkey[tid] = 0; widx[tid] = 0xFFFFFFFFu; }
    __syncthreads();

    // ---- bitonic sort 128 slots, ascending by (key, ~idx) ----
    for (int size = 2; size <= 128; size <<= 1) {
        for (int stride = size >> 1; stride > 0; stride >>= 1) {
            __syncthreads();
            if (tid < 128) {
                int j = tid ^ stride;
                if (j > tid) {
                    uint64_t ki = ((uint64_t)wkey[tid] << 32) | (uint32_t)(~widx[tid]);
                    uint64_t kj = ((uint64_t)wkey[j]   << 32) | (uint32_t)(~widx[j]);
                    bool up = ((tid & size) == 0);
                    if ((ki > kj) == up) {
                        uint32_t t;
                        t = wkey[tid]; wkey[tid] = wkey[j]; wkey[j] = t;
                        t = widx[tid]; widx[tid] = widx[j]; widx[j] = t;
                    }
                }
            }
        }
    }
    __syncthreads();
    if (tid < TOPK) g_topk[b * TOPK + tid] = (int)widx[127 - tid];
}

// ============================================================
// tail: pos_embed + text_proj
// ============================================================
__global__ void tail_kernel(const float* __restrict__ coord_w,
                            const float* __restrict__ coord_b,
                            const float* __restrict__ text_emb,
                            const float* __restrict__ text_w,
                            const float* __restrict__ text_b,
                            float* __restrict__ out) {
    __shared__ float red[256];
    int blk = blockIdx.x, tid = threadIdx.x;
    if (blk < B_ * TOPK) {
        int b = blk / TOPK, k = blk % TOPK;
        int idx = g_topk[b * TOPK + k];
        float ys = (float)(idx / WW) / (float)HH;
        float xs = (float)(idx % WW) / (float)WW;
        float v = xs * coord_w[tid * 2 + 0] + ys * coord_w[tid * 2 + 1] + coord_b[tid];
        out[POS_OFF + (size_t)(b * TOPK + k) * E_ + tid] = v;
    } else {
        int e = blk - B_ * TOPK;
        float s = 0.f;
        for (int i = tid; i < 786; i += 256) s += text_emb[i] * text_w[e * 786 + i];
        red[tid] = s; __syncthreads();
        for (int k2 = 128; k2 > 0; k2 >>= 1) {
            if (tid < k2) red[tid] += red[tid + k2];
            __syncthreads();
        }
        if (tid == 0) {
            float v = red[0] + text_b[e];
            for (int bb = 0; bb < B_; bb++) out[TEXT_OFF + bb * E_ + e] = v;
        }
    }
}

// ============================================================
extern "C" void kernel_launch(void* const* d_in, const int* in_sizes, int n_in,
                              void* d_out, int out_size) {
    const float* feat     = (const float*)d_in[0];
    const float* text_emb = (const float*)d_in[2];
    const float* conv_w   = (const float*)d_in[3];
    const float* conv_b   = (const float*)d_in[4];
    const float* text_w   = (const float*)d_in[5];
    const float* text_b   = (const float*)d_in[6];
    const float* coord_w  = (const float*)d_in[7];
    const float* coord_b  = (const float*)d_in[8];
    float* out = (float*)d_out;

    cudaFuncSetAttribute(gemm_kernel,
                         cudaFuncAttributeMaxDynamicSharedMemorySize, SMEM_TOTAL);

    convh_kernel<<<E_ * CIN / 256, 256>>>(conv_w);
    wbar_kernel<<<4, 128>>>(conv_w, conv_b);
    dim3 g(PTILES, B_);
    gemm_kernel<<<g, 256, SMEM_TOTAL>>>(feat, conv_b, out);
    topk_kernel<<<B_, TPB>>>();
    tail_kernel<<<B_ * TOPK + E_, 256>>>(coord_w, coord_b,
                                         text_emb, text_w, text_b, out);
}